// round 14
// baseline (speedup 1.0000x reference)
#include <cuda_runtime.h>
#include <cstdint>

// Problem constants: x (8, 48, 48, 48, 64) fp32
#define B_   8
#define C_   64
#define N_   110592          // 48*48*48
#define NB_  (C_ * N_)       // 7077888 elements per batch

// Scratch (no allocs allowed): Gram matrix + arrival counters (zero-init)
__device__ float g_G[B_ * C_ * C_];
__device__ int   g_cnt[B_];

// ---------------------------------------------------------------------------
// warp mma m16n8k8 tf32: D(16x8,f32) += A(16x8,tf32 row) * B(8x8,tf32 col)
// fragment layout (lane = 4*g + tg, g=lane>>2, tg=lane&3):
//   a0=(g,tg) a1=(g+8,tg) a2=(g,tg+4) a3=(g+8,tg+4)
//   b0=(tg,g) b1=(tg+4,g)
//   c0=(g,2tg) c1=(g,2tg+1) c2=(g+8,2tg) c3=(g+8,2tg+1)
// ---------------------------------------------------------------------------
__device__ __forceinline__ void mma_tf32(
    float& d0, float& d1, float& d2, float& d3,
    uint32_t a0, uint32_t a1, uint32_t a2, uint32_t a3,
    uint32_t b0, uint32_t b1)
{
    asm volatile(
        "mma.sync.aligned.m16n8k8.row.col.f32.tf32.tf32.f32 "
        "{%0,%1,%2,%3}, {%4,%5,%6,%7}, {%8,%9}, {%0,%1,%2,%3};\n"
        : "+f"(d0), "+f"(d1), "+f"(d2), "+f"(d3)
        : "r"(a0), "r"(a1), "r"(a2), "r"(a3), "r"(b0), "r"(b1));
}

__device__ __forceinline__ uint32_t f2u(float f) { return __float_as_uint(f); }

__device__ __forceinline__ uint32_t smem_u32(const void* p) {
    return (uint32_t)__cvta_generic_to_shared(p);
}
// .cg: bypass L1 allocation (streamed data, never re-read through L1)
__device__ __forceinline__ void cp_async16(uint32_t saddr, const void* gptr) {
    asm volatile("cp.async.cg.shared.global [%0], [%1], 16;\n"
                 :: "r"(saddr), "l"(gptr));
}
__device__ __forceinline__ void cp_commit() {
    asm volatile("cp.async.commit_group;\n");
}
template <int N>
__device__ __forceinline__ void cp_wait() {
    asm volatile("cp.async.wait_group %0;\n" :: "n"(N));
}

__device__ __forceinline__ float sigmoidf_(float s) {
    return 1.0f / (1.0f + __expf(-s));
}

// pack two fp32 as bf16x2 (truncate); unpack to tf32-valid fp32 bit patterns
__device__ __forceinline__ uint32_t pack_bf16x2(float lo, float hi) {
    return (f2u(hi) & 0xFFFF0000u) | (f2u(lo) >> 16);
}
__device__ __forceinline__ uint32_t unpk_lo(uint32_t pk) { return pk << 16; }
__device__ __forceinline__ uint32_t unpk_hi(uint32_t pk) { return pk & 0xFFFF0000u; }

// ---------------------------------------------------------------------------
// Kernel 1: G[b] += K[b] * K[b]^T   (partial Gram per CTA, REDG merge)
// grid (72, 8), block 256, 4 CTAs/SM. 24 chunks of 64 cols, 3-stage pipeline,
// ONE __syncthreads per chunk, prefetch at END of body. Warp tiling: 32x32
// output block x k-parity split (2 LDS per mma).
// smem: 3 x [64][68] fp32 (68 == 4 mod 32 -> frag banks 4g+tg, conflict-free)
// g_G zeroed by previous launch's apply_kernel (static init first call).
// ---------------------------------------------------------------------------
#define S1 68
#define G_CHUNKS 24
__global__ __launch_bounds__(256, 4)
void gram_kernel(const float* __restrict__ x)
{
    extern __shared__ float Ks[];   // 3 * 64 * 68 floats = 52224 B

    const int b    = blockIdx.y;
    const int tid  = threadIdx.x;
    const int warp = tid >> 5;
    const int lane = tid & 31;
    const int g    = lane >> 2;
    const int tg   = lane & 3;
    const int par  = warp >> 2;          // k-step parity (0/1)
    const int blk  = warp & 3;           // which 32x32 block of G
    const int r0   = (blk >> 1) * 32;    // output row base
    const int d0   = (blk & 1) * 32;     // output col base

    const float* xb   = x + (size_t)b * NB_;
    const int   nbase = blockIdx.x * (G_CHUNKS * 64);

    const int lrow = tid >> 4;           // rows tid/16, +16, +32, +48
    const int lc4  = (tid & 15) << 2;

    float acc[2][4][4];
#pragma unroll
    for (int m = 0; m < 2; m++)
#pragma unroll
        for (int i = 0; i < 4; i++)
#pragma unroll
            for (int j = 0; j < 4; j++) acc[m][i][j] = 0.0f;

    // prologue: prefetch chunks 0 and 1
#pragma unroll
    for (int pf = 0; pf < 2; pf++) {
        const float* gsrc = xb + nbase + pf * 64;
        float* buf = Ks + pf * (64 * S1);
#pragma unroll
        for (int it = 0; it < 4; it++) {
            int row = lrow + it * 16;
            cp_async16(smem_u32(&buf[row * S1 + lc4]),
                       gsrc + (size_t)row * N_ + lc4);
        }
        cp_commit();
    }

    for (int ch = 0; ch < G_CHUNKS; ch++) {
        cp_wait<1>();          // chunk ch resident
        __syncthreads();

        const float* buf = Ks + (ch % 3) * (64 * S1);
#pragma unroll
        for (int ksl = 0; ksl < 4; ksl++) {
            const int kk = (ksl * 2 + par) * 8;
            uint32_t a[2][4];
#pragma unroll
            for (int m = 0; m < 2; m++) {
                const int rm = r0 + m * 16;
                a[m][0] = f2u(buf[(rm + g)     * S1 + kk + tg]);
                a[m][1] = f2u(buf[(rm + 8 + g) * S1 + kk + tg]);
                a[m][2] = f2u(buf[(rm + g)     * S1 + kk + tg + 4]);
                a[m][3] = f2u(buf[(rm + 8 + g) * S1 + kk + tg + 4]);
            }
#pragma unroll
            for (int nb = 0; nb < 4; nb++) {
                const int dr = d0 + nb * 8 + g;
                uint32_t b0 = f2u(buf[dr * S1 + kk + tg]);
                uint32_t b1 = f2u(buf[dr * S1 + kk + tg + 4]);
#pragma unroll
                for (int m = 0; m < 2; m++)
                    mma_tf32(acc[m][nb][0], acc[m][nb][1],
                             acc[m][nb][2], acc[m][nb][3],
                             a[m][0], a[m][1], a[m][2], a[m][3], b0, b1);
            }
        }

        // prefetch chunk ch+2 (off the critical compute-entry path)
        if (ch + 2 < G_CHUNKS) {
            const float* gsrc = xb + nbase + (ch + 2) * 64;
            float* pbuf = Ks + ((ch + 2) % 3) * (64 * S1);
#pragma unroll
            for (int it = 0; it < 4; it++) {
                int row = lrow + it * 16;
                cp_async16(smem_u32(&pbuf[row * S1 + lc4]),
                           gsrc + (size_t)row * N_ + lc4);
            }
        }
        cp_commit();           // always commit -> uniform wait counting
    }

    // merge partials (parity pairs + 72 CTAs hit the same entries)
    float* Gb = g_G + b * (C_ * C_);
#pragma unroll
    for (int m = 0; m < 2; m++) {
        const int rA = r0 + m * 16 + g;
        const int rB = rA + 8;
#pragma unroll
        for (int nb = 0; nb < 4; nb++) {
            const int d = d0 + nb * 8 + tg * 2;
            atomicAdd(&Gb[rA * C_ + d],     acc[m][nb][0]);
            atomicAdd(&Gb[rA * C_ + d + 1], acc[m][nb][1]);
            atomicAdd(&Gb[rB * C_ + d],     acc[m][nb][2]);
            atomicAdd(&Gb[rB * C_ + d + 1], acc[m][nb][3]);
        }
    }
}

// ---------------------------------------------------------------------------
// Kernel 2: out = x + gamma * (sigmoid(G@G) @ K)    [m3+sigmoid fused]
// grid (54, 8), block 256, 3 CTAs/SM. 32 tiles of 64 cols, 3-stage cp.async
// pipeline, ONE sync per tile, prefetch at end of body.
// NEW main-loop warp tiling: warp = (32-row c-block) x (16-col n-quarter):
//   cblk = warp&1 -> rows cblk*32..+32 (two m16 groups)
//   nq   = warp>>1 -> cols nq*16..+16 (two n8 blocks)
// Each B fragment feeds 32 output rows (was 16) -> B-frag smem traffic and
// LDS count in the hot loop HALVE. Affinity fragments for the doubled M are
// held as bf16x2-packed pairs (32 regs; unpacked with 2 ALU ops each).
// bf16 affinity precision: sigmoid-saturated ~0/1 values; worst-case 0.4%
// midrange error scaled by gamma=1e-4 -> ~1e-8 relative on the output.
// B-frag banks: 8tg + g + const -> bijective, conflict-free (S3=72==8 mod 32)
// GA (G/affinity [64][68]) overlays buffer 2 (first overwritten by tile-2
// prefetch, ordered after the pre-loop syncs). Last-arriver CTA re-zeroes
// g_G[b] (reads barrier-ordered before counter increment -> race-free).
// ---------------------------------------------------------------------------
#define S3 72
#define SA 68
#define A_TILES 32
__global__ __launch_bounds__(256, 3)
void apply_kernel(const float* __restrict__ x, float* __restrict__ out,
                  const float* __restrict__ gammap)
{
    extern __shared__ float Ks[];        // 3 * 64 * 72 floats = 55296 B
    float* GA = Ks + 2 * (64 * S3);      // G / affinity region, [64][SA]
    __shared__ int sm_last;

    const int b    = blockIdx.y;
    const int tid  = threadIdx.x;
    const int warp = tid >> 5;
    const int lane = tid & 31;
    const int g    = lane >> 2;
    const int tg   = lane & 3;
    // affinity-phase mapping (16 rows x 32 cols per warp)
    const int c0   = (warp >> 1) * 16;
    const int nc0  = (warp & 1) * 32;
    // main-loop mapping (32 rows x 16 cols per warp)
    const int cblk = warp & 1;           // 32-row block
    const int nq   = warp >> 1;          // 16-col quarter
    const int rb0  = cblk * 32;

    const float gamma = gammap[0];
    const float* xb   = x + (size_t)b * NB_;
    float*       ob   = out + (size_t)b * NB_;
    const int   nbase = blockIdx.x * (A_TILES * 64);

    const int lrow = tid >> 4;
    const int lc4  = (tid & 15) << 2;

    // prologue: prefetch tiles 0 and 1 (overlaps with affinity phase below)
#pragma unroll
    for (int pf = 0; pf < 2; pf++) {
        const float* gsrc = xb + nbase + pf * 64;
        float* buf = Ks + pf * (64 * S3);
#pragma unroll
        for (int it = 0; it < 4; it++) {
            int row = lrow + it * 16;
            cp_async16(smem_u32(&buf[row * S3 + lc4]),
                       gsrc + (size_t)row * N_ + lc4);
        }
        cp_commit();
    }

    // ---- fused affinity = sigmoid(G @ G) ----
    for (int i = tid; i < C_ * C_; i += 256)
        GA[(i >> 6) * SA + (i & 63)] = g_G[b * C_ * C_ + i];
    __syncthreads();   // all reads of g_G done for every thread of this CTA

    // arrival counter: g_G[b] may be zeroed once all 54 CTAs have read it
    if (tid == 0)
        sm_last = (atomicAdd(&g_cnt[b], 1) == (int)gridDim.x - 1) ? 1 : 0;

    {
        float mac[4][4];
#pragma unroll
        for (int i = 0; i < 4; i++)
#pragma unroll
            for (int j = 0; j < 4; j++) mac[i][j] = 0.0f;

#pragma unroll
        for (int kd = 0; kd < 8; kd++) {
            const int d0 = kd * 8;
            uint32_t a0 = f2u(GA[(c0 + g)     * SA + d0 + tg]);
            uint32_t a1 = f2u(GA[(c0 + 8 + g) * SA + d0 + tg]);
            uint32_t a2 = f2u(GA[(c0 + g)     * SA + d0 + tg + 4]);
            uint32_t a3 = f2u(GA[(c0 + 8 + g) * SA + d0 + tg + 4]);
#pragma unroll
            for (int nb = 0; nb < 4; nb++) {
                const int col = nc0 + nb * 8;
                uint32_t b0 = f2u(GA[(d0 + tg)     * SA + col + g]);
                uint32_t b1 = f2u(GA[(d0 + tg + 4) * SA + col + g]);
                mma_tf32(mac[nb][0], mac[nb][1], mac[nb][2], mac[nb][3],
                         a0, a1, a2, a3, b0, b1);
            }
        }
        __syncthreads();   // all reads of G done before overwrite w/ affinity

#pragma unroll
        for (int nb = 0; nb < 4; nb++) {
            const int col = nc0 + nb * 8 + 2 * tg;
            GA[(c0 + g)     * SA + col]     = sigmoidf_(mac[nb][0]);
            GA[(c0 + g)     * SA + col + 1] = sigmoidf_(mac[nb][1]);
            GA[(c0 + 8 + g) * SA + col]     = sigmoidf_(mac[nb][2]);
            GA[(c0 + 8 + g) * SA + col + 1] = sigmoidf_(mac[nb][3]);
        }
    }
    __syncthreads();

    // hoist affinity fragments for the 32-row block, packed bf16x2.
    // group grp (rows rb0+grp*16..+16): a0=(R+g,d0+tg) a1=(R+8+g,d0+tg)
    //   a2=(R+g,d0+tg+4) a3=(R+8+g,d0+tg+4)
    // pk[kd][grp][0] packs (a0,a2) [row R+g], pk[kd][grp][1] packs (a1,a3).
    uint32_t afp[8][2][2];
#pragma unroll
    for (int kd = 0; kd < 8; kd++) {
        const int d0 = kd * 8;
#pragma unroll
        for (int grp = 0; grp < 2; grp++) {
            const int R = rb0 + grp * 16;
            float a0 = GA[(R + g)     * SA + d0 + tg];
            float a1 = GA[(R + 8 + g) * SA + d0 + tg];
            float a2 = GA[(R + g)     * SA + d0 + tg + 4];
            float a3 = GA[(R + 8 + g) * SA + d0 + tg + 4];
            afp[kd][grp][0] = pack_bf16x2(a0, a2);
            afp[kd][grp][1] = pack_bf16x2(a1, a3);
        }
    }

    // last arriver zeroes g_G[b] for the next launch and resets the counter
    if (sm_last) {
        for (int i = tid; i < C_ * C_; i += 256)
            g_G[b * C_ * C_ + i] = 0.0f;
        if (tid == 0) g_cnt[b] = 0;
    }

    // ---- main loop: one sync per tile ----
    for (int t = 0; t < A_TILES; t++) {
        cp_wait<1>();              // tile t resident
        __syncthreads();

        const float* buf = Ks + (t % 3) * (64 * S3);

        float acc[2][2][4];        // [grp][nb][4]
#pragma unroll
        for (int m = 0; m < 2; m++)
#pragma unroll
            for (int i = 0; i < 2; i++)
#pragma unroll
                for (int j = 0; j < 4; j++) acc[m][i][j] = 0.0f;

#pragma unroll
        for (int kd = 0; kd < 8; kd++) {
            const int d0 = kd * 8;
            uint32_t a[2][4];
#pragma unroll
            for (int grp = 0; grp < 2; grp++) {
                a[grp][0] = unpk_lo(afp[kd][grp][0]);
                a[grp][1] = unpk_lo(afp[kd][grp][1]);
                a[grp][2] = unpk_hi(afp[kd][grp][0]);
                a[grp][3] = unpk_hi(afp[kd][grp][1]);
            }
#pragma unroll
            for (int nb = 0; nb < 2; nb++) {
                const int col = nq * 16 + nb * 8;
                uint32_t b0 = f2u(buf[(d0 + tg)     * S3 + col + g]);
                uint32_t b1 = f2u(buf[(d0 + tg + 4) * S3 + col + g]);
#pragma unroll
                for (int grp = 0; grp < 2; grp++)
                    mma_tf32(acc[grp][nb][0], acc[grp][nb][1],
                             acc[grp][nb][2], acc[grp][nb][3],
                             a[grp][0], a[grp][1], a[grp][2], a[grp][3],
                             b0, b1);
            }
        }

        // epilogue: out = x + gamma * weights (x re-read from smem tile)
        const int n0 = nbase + t * 64;
#pragma unroll
        for (int grp = 0; grp < 2; grp++) {
            const int r0 = rb0 + grp * 16 + g;
            const int r1 = r0 + 8;
#pragma unroll
            for (int nb = 0; nb < 2; nb++) {
                const int col = nq * 16 + nb * 8 + tg * 2;
                float2 x0 = *(const float2*)&buf[r0 * S3 + col];
                float2 x1 = *(const float2*)&buf[r1 * S3 + col];
                float2 o0 = make_float2(fmaf(gamma, acc[grp][nb][0], x0.x),
                                        fmaf(gamma, acc[grp][nb][1], x0.y));
                float2 o1 = make_float2(fmaf(gamma, acc[grp][nb][2], x1.x),
                                        fmaf(gamma, acc[grp][nb][3], x1.y));
                *(float2*)(ob + (size_t)r0 * N_ + n0 + col) = o0;
                *(float2*)(ob + (size_t)r1 * N_ + n0 + col) = o1;
            }
        }

        // prefetch tile t+2 (off the critical compute-entry path)
        if (t + 2 < A_TILES) {
            const float* gsrc = xb + nbase + (t + 2) * 64;
            float* pbuf = Ks + ((t + 2) % 3) * (64 * S3);
#pragma unroll
            for (int it = 0; it < 4; it++) {
                int row = lrow + it * 16;
                cp_async16(smem_u32(&pbuf[row * S3 + lc4]),
                           gsrc + (size_t)row * N_ + lc4);
            }
        }
        cp_commit();               // always commit -> uniform wait counting
    }
}

// ---------------------------------------------------------------------------
// Launch
// ---------------------------------------------------------------------------
extern "C" void kernel_launch(void* const* d_in, const int* in_sizes, int n_in,
                              void* d_out, int out_size)
{
    const float* x     = (const float*)d_in[0];
    const float* gamma = (const float*)d_in[1];
    float*       out   = (float*)d_out;

    (void)in_sizes; (void)n_in; (void)out_size;

    const int smem1 = 3 * 64 * S1 * (int)sizeof(float);   // 52224
    const int smem3 = 3 * 64 * S3 * (int)sizeof(float);   // 55296

    cudaFuncSetAttribute(gram_kernel,
                         cudaFuncAttributeMaxDynamicSharedMemorySize, smem1);
    cudaFuncSetAttribute(apply_kernel,
                         cudaFuncAttributeMaxDynamicSharedMemorySize, smem3);

    dim3 grid1(72, B_);                   // 72 * 24 chunks * 64 = 110592
    gram_kernel<<<grid1, 256, smem1>>>(x);

    dim3 grid3(54, B_);                   // 54 * 32 tiles * 64 = 110592
    apply_kernel<<<grid3, 256, smem3>>>(x, out, gamma);
}

// round 15
// speedup vs baseline: 1.0740x; 1.0740x over previous
#include <cuda_runtime.h>
#include <cstdint>

// Problem constants: x (8, 48, 48, 48, 64) fp32
#define B_   8
#define C_   64
#define N_   110592          // 48*48*48
#define NB_  (C_ * N_)       // 7077888 elements per batch

// Scratch (no allocs allowed): Gram matrix + arrival counters (zero-init)
__device__ float g_G[B_ * C_ * C_];
__device__ int   g_cnt[B_];

// ---------------------------------------------------------------------------
// warp mma m16n8k8 tf32: D(16x8,f32) += A(16x8,tf32 row) * B(8x8,tf32 col)
// fragment layout (lane = 4*g + tg, g=lane>>2, tg=lane&3):
//   a0=(g,tg) a1=(g+8,tg) a2=(g,tg+4) a3=(g+8,tg+4)
//   b0=(tg,g) b1=(tg+4,g)
//   c0=(g,2tg) c1=(g,2tg+1) c2=(g+8,2tg) c3=(g+8,2tg+1)
// ---------------------------------------------------------------------------
__device__ __forceinline__ void mma_tf32(
    float& d0, float& d1, float& d2, float& d3,
    uint32_t a0, uint32_t a1, uint32_t a2, uint32_t a3,
    uint32_t b0, uint32_t b1)
{
    asm volatile(
        "mma.sync.aligned.m16n8k8.row.col.f32.tf32.tf32.f32 "
        "{%0,%1,%2,%3}, {%4,%5,%6,%7}, {%8,%9}, {%0,%1,%2,%3};\n"
        : "+f"(d0), "+f"(d1), "+f"(d2), "+f"(d3)
        : "r"(a0), "r"(a1), "r"(a2), "r"(a3), "r"(b0), "r"(b1));
}

__device__ __forceinline__ uint32_t f2u(float f) { return __float_as_uint(f); }

__device__ __forceinline__ uint32_t smem_u32(const void* p) {
    return (uint32_t)__cvta_generic_to_shared(p);
}
// .cg: bypass L1 allocation (streamed data, never re-read through L1)
__device__ __forceinline__ void cp_async16(uint32_t saddr, const void* gptr) {
    asm volatile("cp.async.cg.shared.global [%0], [%1], 16;\n"
                 :: "r"(saddr), "l"(gptr));
}
__device__ __forceinline__ void cp_commit() {
    asm volatile("cp.async.commit_group;\n");
}
template <int N>
__device__ __forceinline__ void cp_wait() {
    asm volatile("cp.async.wait_group %0;\n" :: "n"(N));
}

// ---- bulk-copy (UBLKCP/TMA path) + mbarrier helpers ----
__device__ __forceinline__ void mbar_init(uint32_t mbar, uint32_t count) {
    asm volatile("mbarrier.init.shared.b64 [%0], %1;"
                 :: "r"(mbar), "r"(count) : "memory");
}
__device__ __forceinline__ void mbar_expect_tx(uint32_t mbar, uint32_t bytes) {
    asm volatile("mbarrier.arrive.expect_tx.shared.b64 _, [%0], %1;"
                 :: "r"(mbar), "r"(bytes) : "memory");
}
__device__ __forceinline__ void mbar_wait(uint32_t mbar, uint32_t parity) {
    asm volatile(
        "{\n\t"
        ".reg .pred P1;\n\t"
        "WAIT_LOOP_%=:\n\t"
        "mbarrier.try_wait.parity.acquire.cta.shared::cta.b64 P1, [%0], %1;\n\t"
        "@P1 bra.uni WAIT_DONE_%=;\n\t"
        "bra.uni WAIT_LOOP_%=;\n\t"
        "WAIT_DONE_%=:\n\t"
        "}"
        :: "r"(mbar), "r"(parity) : "memory");
}
// 1D bulk copy global -> shared::cta, completion via mbarrier complete_tx
__device__ __forceinline__ void bulk_g2s(uint32_t sdst, const void* gsrc,
                                         uint32_t bytes, uint32_t mbar) {
    asm volatile(
        "cp.async.bulk.shared::cta.global.mbarrier::complete_tx::bytes "
        "[%0], [%1], %2, [%3];"
        :: "r"(sdst), "l"(gsrc), "r"(bytes), "r"(mbar) : "memory");
}

__device__ __forceinline__ float sigmoidf_(float s) {
    return 1.0f / (1.0f + __expf(-s));
}

// ---------------------------------------------------------------------------
// Kernel 1: G[b] += K[b] * K[b]^T   (partial Gram per CTA, REDG merge)
// grid (72, 8), block 256, 4 CTAs/SM. 24 chunks of 64 cols, 3-stage pipeline.
// NEW FILL PATH: per chunk, 64 x cp.async.bulk of 256B (one per tile row,
// issued by tid 0) into the stage buffer; completion via mbarrier expect_tx
// (16KB). Replaces 1024 per-lane LDGSTS -> rides the TMA/LTS bulk path that
// sustains ~6300 B/cyc instead of the ~2300 B/cyc LDGSTS plateau.
// Pipeline (ONE __syncthreads per chunk, prefetch at END of body):
//   mbar_wait(stage ch%3, parity (ch/3)&1); sync; compute(ch);
//   tid0: expect_tx + 64 bulks for ch+2
// Safety: tid0 issues the ch+2 fill only after the body-top sync of chunk ch,
// which every warp reaches only after finishing compute(ch-1) -- the last
// reader of buffer (ch+2)%3 == (ch-1)%3.
// Warp tiling: 32x32 output block x k-parity split (2 LDS per mma).
// smem: 3 x [64][68] fp32 (68 == 4 mod 32 -> frag banks 4g+tg conflict-free;
// row stride 272B is 16B-aligned for bulk dst).
// g_G zeroed by previous launch's apply_kernel (static init first call).
// ---------------------------------------------------------------------------
#define S1 68
#define G_CHUNKS 24
#define G_TILE_BYTES (64 * 256)
__global__ __launch_bounds__(256, 4)
void gram_kernel(const float* __restrict__ x)
{
    extern __shared__ float Ks[];   // 3 * 64 * 68 floats = 52224 B
    __shared__ uint64_t mb[3];

    const int b    = blockIdx.y;
    const int tid  = threadIdx.x;
    const int warp = tid >> 5;
    const int lane = tid & 31;
    const int g    = lane >> 2;
    const int tg   = lane & 3;
    const int par  = warp >> 2;          // k-step parity (0/1)
    const int blk  = warp & 3;           // which 32x32 block of G
    const int r0   = (blk >> 1) * 32;    // output row base
    const int d0   = (blk & 1) * 32;     // output col base

    const float* xb   = x + (size_t)b * NB_;
    const int   nbase = blockIdx.x * (G_CHUNKS * 64);

    // mbarrier init (one per stage, single arrival = the expect_tx arrive)
    if (tid == 0) {
        mbar_init(smem_u32(&mb[0]), 1);
        mbar_init(smem_u32(&mb[1]), 1);
        mbar_init(smem_u32(&mb[2]), 1);
    }
    __syncthreads();

    float acc[2][4][4];
#pragma unroll
    for (int m = 0; m < 2; m++)
#pragma unroll
        for (int i = 0; i < 4; i++)
#pragma unroll
            for (int j = 0; j < 4; j++) acc[m][i][j] = 0.0f;

    // prologue: tid 0 launches bulk fills for chunks 0 and 1
    if (tid == 0) {
#pragma unroll
        for (int pf = 0; pf < 2; pf++) {
            const uint32_t mbar = smem_u32(&mb[pf]);
            mbar_expect_tx(mbar, G_TILE_BYTES);
            const float* gsrc = xb + nbase + pf * 64;
            float* buf = Ks + pf * (64 * S1);
            for (int row = 0; row < 64; row++)
                bulk_g2s(smem_u32(&buf[row * S1]),
                         gsrc + (size_t)row * N_, 256, mbar);
        }
    }

    for (int ch = 0; ch < G_CHUNKS; ch++) {
        mbar_wait(smem_u32(&mb[ch % 3]), (ch / 3) & 1);   // chunk ch resident
        __syncthreads();   // also: all warps finished compute(ch-1)

        const float* buf = Ks + (ch % 3) * (64 * S1);
#pragma unroll
        for (int ksl = 0; ksl < 4; ksl++) {
            const int kk = (ksl * 2 + par) * 8;
            uint32_t a[2][4];
#pragma unroll
            for (int m = 0; m < 2; m++) {
                const int rm = r0 + m * 16;
                a[m][0] = f2u(buf[(rm + g)     * S1 + kk + tg]);
                a[m][1] = f2u(buf[(rm + 8 + g) * S1 + kk + tg]);
                a[m][2] = f2u(buf[(rm + g)     * S1 + kk + tg + 4]);
                a[m][3] = f2u(buf[(rm + 8 + g) * S1 + kk + tg + 4]);
            }
#pragma unroll
            for (int nb = 0; nb < 4; nb++) {
                const int dr = d0 + nb * 8 + g;
                uint32_t b0 = f2u(buf[dr * S1 + kk + tg]);
                uint32_t b1 = f2u(buf[dr * S1 + kk + tg + 4]);
#pragma unroll
                for (int m = 0; m < 2; m++)
                    mma_tf32(acc[m][nb][0], acc[m][nb][1],
                             acc[m][nb][2], acc[m][nb][3],
                             a[m][0], a[m][1], a[m][2], a[m][3], b0, b1);
            }
        }

        // prefetch chunk ch+2 via bulk path (tid 0 only)
        if (tid == 0 && ch + 2 < G_CHUNKS) {
            const uint32_t mbar = smem_u32(&mb[(ch + 2) % 3]);
            mbar_expect_tx(mbar, G_TILE_BYTES);
            const float* gsrc = xb + nbase + (ch + 2) * 64;
            float* pbuf = Ks + ((ch + 2) % 3) * (64 * S1);
            for (int row = 0; row < 64; row++)
                bulk_g2s(smem_u32(&pbuf[row * S1]),
                         gsrc + (size_t)row * N_, 256, mbar);
        }
    }

    // merge partials (parity pairs + 72 CTAs hit the same entries)
    float* Gb = g_G + b * (C_ * C_);
#pragma unroll
    for (int m = 0; m < 2; m++) {
        const int rA = r0 + m * 16 + g;
        const int rB = rA + 8;
#pragma unroll
        for (int nb = 0; nb < 4; nb++) {
            const int d = d0 + nb * 8 + tg * 2;
            atomicAdd(&Gb[rA * C_ + d],     acc[m][nb][0]);
            atomicAdd(&Gb[rA * C_ + d + 1], acc[m][nb][1]);
            atomicAdd(&Gb[rB * C_ + d],     acc[m][nb][2]);
            atomicAdd(&Gb[rB * C_ + d + 1], acc[m][nb][3]);
        }
    }
}

// ---------------------------------------------------------------------------
// Kernel 2: out = x + gamma * (sigmoid(G@G) @ K)    [m3+sigmoid fused]
// EXACT revert to the proven R9/R12 apply (best measured): grid (54, 8),
// block 256, 3 CTAs/SM, 32 tiles of 64 cols, 3-stage cp.async pipeline,
// ONE sync per tile, prefetch at end of body, affinity fragments in regs.
// GA (G/affinity [64][68]) overlays buffer 2. Last-arriver CTA re-zeroes
// g_G[b] (reads barrier-ordered before counter increment -> race-free).
// smem: 3 x Ks[64][72] (72 == 8 mod 32 -> B-frag banks 8tg+g conflict-free).
// ---------------------------------------------------------------------------
#define S3 72
#define SA 68
#define A_TILES 32
__global__ __launch_bounds__(256, 3)
void apply_kernel(const float* __restrict__ x, float* __restrict__ out,
                  const float* __restrict__ gammap)
{
    extern __shared__ float Ks[];        // 3 * 64 * 72 floats = 55296 B
    float* GA = Ks + 2 * (64 * S3);      // G / affinity region, [64][SA]
    __shared__ int sm_last;

    const int b    = blockIdx.y;
    const int tid  = threadIdx.x;
    const int warp = tid >> 5;
    const int lane = tid & 31;
    const int g    = lane >> 2;
    const int tg   = lane & 3;
    const int c0   = (warp >> 1) * 16;   // c-block (16 rows)
    const int nc0  = (warp & 1) * 32;    // n-half (32 cols)

    const float gamma = gammap[0];
    const float* xb   = x + (size_t)b * NB_;
    float*       ob   = out + (size_t)b * NB_;
    const int   nbase = blockIdx.x * (A_TILES * 64);

    const int lrow = tid >> 4;
    const int lc4  = (tid & 15) << 2;

    // prologue: prefetch tiles 0 and 1 (overlaps with affinity phase below)
#pragma unroll
    for (int pf = 0; pf < 2; pf++) {
        const float* gsrc = xb + nbase + pf * 64;
        float* buf = Ks + pf * (64 * S3);
#pragma unroll
        for (int it = 0; it < 4; it++) {
            int row = lrow + it * 16;
            cp_async16(smem_u32(&buf[row * S3 + lc4]),
                       gsrc + (size_t)row * N_ + lc4);
        }
        cp_commit();
    }

    // ---- fused affinity = sigmoid(G @ G) ----
    for (int i = tid; i < C_ * C_; i += 256)
        GA[(i >> 6) * SA + (i & 63)] = g_G[b * C_ * C_ + i];
    __syncthreads();   // all reads of g_G done for every thread of this CTA

    // arrival counter: g_G[b] may be zeroed once all 54 CTAs have read it
    if (tid == 0)
        sm_last = (atomicAdd(&g_cnt[b], 1) == (int)gridDim.x - 1) ? 1 : 0;

    {
        float mac[4][4];
#pragma unroll
        for (int i = 0; i < 4; i++)
#pragma unroll
            for (int j = 0; j < 4; j++) mac[i][j] = 0.0f;

#pragma unroll
        for (int kd = 0; kd < 8; kd++) {
            const int d0 = kd * 8;
            uint32_t a0 = f2u(GA[(c0 + g)     * SA + d0 + tg]);
            uint32_t a1 = f2u(GA[(c0 + 8 + g) * SA + d0 + tg]);
            uint32_t a2 = f2u(GA[(c0 + g)     * SA + d0 + tg + 4]);
            uint32_t a3 = f2u(GA[(c0 + 8 + g) * SA + d0 + tg + 4]);
#pragma unroll
            for (int nb = 0; nb < 4; nb++) {
                const int col = nc0 + nb * 8;
                uint32_t b0 = f2u(GA[(d0 + tg)     * SA + col + g]);
                uint32_t b1 = f2u(GA[(d0 + tg + 4) * SA + col + g]);
                mma_tf32(mac[nb][0], mac[nb][1], mac[nb][2], mac[nb][3],
                         a0, a1, a2, a3, b0, b1);
            }
        }
        __syncthreads();   // all reads of G done before overwrite w/ affinity

#pragma unroll
        for (int nb = 0; nb < 4; nb++) {
            const int col = nc0 + nb * 8 + 2 * tg;
            GA[(c0 + g)     * SA + col]     = sigmoidf_(mac[nb][0]);
            GA[(c0 + g)     * SA + col + 1] = sigmoidf_(mac[nb][1]);
            GA[(c0 + 8 + g) * SA + col]     = sigmoidf_(mac[nb][2]);
            GA[(c0 + 8 + g) * SA + col + 1] = sigmoidf_(mac[nb][3]);
        }
    }
    __syncthreads();

    // hoist affinity fragments to registers (tile-invariant). 32 regs.
    uint32_t af[8][4];
#pragma unroll
    for (int kd = 0; kd < 8; kd++) {
        const int d0 = kd * 8;
        af[kd][0] = f2u(GA[(c0 + g)     * SA + d0 + tg]);
        af[kd][1] = f2u(GA[(c0 + 8 + g) * SA + d0 + tg]);
        af[kd][2] = f2u(GA[(c0 + g)     * SA + d0 + tg + 4]);
        af[kd][3] = f2u(GA[(c0 + 8 + g) * SA + d0 + tg + 4]);
    }

    // last arriver zeroes g_G[b] for the next launch and resets the counter
    if (sm_last) {
        for (int i = tid; i < C_ * C_; i += 256)
            g_G[b * C_ * C_ + i] = 0.0f;
        if (tid == 0) g_cnt[b] = 0;
    }

    // ---- main loop: one sync per tile ----
    for (int t = 0; t < A_TILES; t++) {
        cp_wait<1>();              // tile t resident
        __syncthreads();

        const float* buf = Ks + (t % 3) * (64 * S3);

        float acc[4][4];
#pragma unroll
        for (int i = 0; i < 4; i++)
#pragma unroll
            for (int j = 0; j < 4; j++) acc[i][j] = 0.0f;

#pragma unroll
        for (int kd = 0; kd < 8; kd++) {
            const int d0 = kd * 8;
#pragma unroll
            for (int nb = 0; nb < 4; nb++) {
                const int col = nc0 + nb * 8;
                uint32_t b0 = f2u(buf[(d0 + tg)     * S3 + col + g]);
                uint32_t b1 = f2u(buf[(d0 + tg + 4) * S3 + col + g]);
                mma_tf32(acc[nb][0], acc[nb][1], acc[nb][2], acc[nb][3],
                         af[kd][0], af[kd][1], af[kd][2], af[kd][3], b0, b1);
            }
        }

        // epilogue: out = x + gamma * weights (x re-read from smem tile)
        const int n0 = nbase + t * 64;
#pragma unroll
        for (int nb = 0; nb < 4; nb++) {
            const int col = nc0 + nb * 8 + tg * 2;
            const int r0 = c0 + g;
            const int r1 = c0 + 8 + g;
            float2 x0 = *(const float2*)&buf[r0 * S3 + col];
            float2 x1 = *(const float2*)&buf[r1 * S3 + col];
            float2 o0 = make_float2(fmaf(gamma, acc[nb][0], x0.x),
                                    fmaf(gamma, acc[nb][1], x0.y));
            float2 o1 = make_float2(fmaf(gamma, acc[nb][2], x1.x),
                                    fmaf(gamma, acc[nb][3], x1.y));
            *(float2*)(ob + (size_t)r0 * N_ + n0 + col) = o0;
            *(float2*)(ob + (size_t)r1 * N_ + n0 + col) = o1;
        }

        // prefetch tile t+2 (off the critical compute-entry path)
        if (t + 2 < A_TILES) {
            const float* gsrc = xb + nbase + (t + 2) * 64;
            float* pbuf = Ks + ((t + 2) % 3) * (64 * S3);
#pragma unroll
            for (int it = 0; it < 4; it++) {
                int row = lrow + it * 16;
                cp_async16(smem_u32(&pbuf[row * S3 + lc4]),
                           gsrc + (size_t)row * N_ + lc4);
            }
        }
        cp_commit();               // always commit -> uniform wait counting
    }
}

// ---------------------------------------------------------------------------
// Launch
// ---------------------------------------------------------------------------
extern "C" void kernel_launch(void* const* d_in, const int* in_sizes, int n_in,
                              void* d_out, int out_size)
{
    const float* x     = (const float*)d_in[0];
    const float* gamma = (const float*)d_in[1];
    float*       out   = (float*)d_out;

    (void)in_sizes; (void)n_in; (void)out_size;

    const int smem1 = 3 * 64 * S1 * (int)sizeof(float);   // 52224
    const int smem3 = 3 * 64 * S3 * (int)sizeof(float);   // 55296

    cudaFuncSetAttribute(gram_kernel,
                         cudaFuncAttributeMaxDynamicSharedMemorySize, smem1);
    cudaFuncSetAttribute(apply_kernel,
                         cudaFuncAttributeMaxDynamicSharedMemorySize, smem3);

    dim3 grid1(72, B_);                   // 72 * 24 chunks * 64 = 110592
    gram_kernel<<<grid1, 256, smem1>>>(x);

    dim3 grid3(54, B_);                   // 54 * 32 tiles * 64 = 110592
    apply_kernel<<<grid3, 256, smem3>>>(x, out, gamma);
}

// round 16
// speedup vs baseline: 1.1619x; 1.0818x over previous
#include <cuda_runtime.h>
#include <cstdint>

// Problem constants: x (8, 48, 48, 48, 64) fp32
#define B_   8
#define C_   64
#define N_   110592          // 48*48*48
#define NB_  (C_ * N_)       // 7077888 elements per batch

// Scratch (no allocs allowed): Gram matrix + arrival counters (zero-init)
__device__ float g_G[B_ * C_ * C_];
__device__ int   g_cnt[B_];

// ---------------------------------------------------------------------------
// warp mma m16n8k8 tf32: D(16x8,f32) += A(16x8,tf32 row) * B(8x8,tf32 col)
// fragment layout (lane = 4*g + tg, g=lane>>2, tg=lane&3):
//   a0=(g,tg) a1=(g+8,tg) a2=(g,tg+4) a3=(g+8,tg+4)
//   b0=(tg,g) b1=(tg+4,g)
//   c0=(g,2tg) c1=(g,2tg+1) c2=(g+8,2tg) c3=(g+8,2tg+1)
// ---------------------------------------------------------------------------
__device__ __forceinline__ void mma_tf32(
    float& d0, float& d1, float& d2, float& d3,
    uint32_t a0, uint32_t a1, uint32_t a2, uint32_t a3,
    uint32_t b0, uint32_t b1)
{
    asm volatile(
        "mma.sync.aligned.m16n8k8.row.col.f32.tf32.tf32.f32 "
        "{%0,%1,%2,%3}, {%4,%5,%6,%7}, {%8,%9}, {%0,%1,%2,%3};\n"
        : "+f"(d0), "+f"(d1), "+f"(d2), "+f"(d3)
        : "r"(a0), "r"(a1), "r"(a2), "r"(a3), "r"(b0), "r"(b1));
}

__device__ __forceinline__ uint32_t f2u(float f) { return __float_as_uint(f); }

__device__ __forceinline__ uint32_t smem_u32(const void* p) {
    return (uint32_t)__cvta_generic_to_shared(p);
}
// .cg: bypass L1 allocation (streamed data, never re-read through L1)
__device__ __forceinline__ void cp_async16(uint32_t saddr, const void* gptr) {
    asm volatile("cp.async.cg.shared.global [%0], [%1], 16;\n"
                 :: "r"(saddr), "l"(gptr));
}
__device__ __forceinline__ void cp_commit() {
    asm volatile("cp.async.commit_group;\n");
}
template <int N>
__device__ __forceinline__ void cp_wait() {
    asm volatile("cp.async.wait_group %0;\n" :: "n"(N));
}

__device__ __forceinline__ float sigmoidf_(float s) {
    return 1.0f / (1.0f + __expf(-s));
}

// pack two fp32 as bf16x2 (truncate); unpack to tf32-valid fp32 bit patterns
__device__ __forceinline__ uint32_t pack_bf16x2(float lo, float hi) {
    return (f2u(hi) & 0xFFFF0000u) | (f2u(lo) >> 16);
}
__device__ __forceinline__ uint32_t unpk_lo(uint32_t pk) { return pk << 16; }
__device__ __forceinline__ uint32_t unpk_hi(uint32_t pk) { return pk & 0xFFFF0000u; }

// ---------------------------------------------------------------------------
// Kernel 1: G[b] += K[b] * K[b]^T   (partial Gram per CTA, REDG merge)
// PROVEN R12 version (LDGSTS fill; bulk-copy variant measured slower).
// grid (72, 8), block 256, 4 CTAs/SM. 24 chunks of 64 cols, 3-stage pipeline,
// ONE __syncthreads per chunk, prefetch at END of body. Warp tiling: 32x32
// output block x k-parity split (2 LDS per mma).
// smem: 3 x [64][68] fp32 (68 == 4 mod 32 -> frag banks 4g+tg, conflict-free)
// g_G zeroed by previous launch's apply_kernel (static init first call).
// ---------------------------------------------------------------------------
#define S1 68
#define G_CHUNKS 24
__global__ __launch_bounds__(256, 4)
void gram_kernel(const float* __restrict__ x)
{
    extern __shared__ float Ks[];   // 3 * 64 * 68 floats = 52224 B

    const int b    = blockIdx.y;
    const int tid  = threadIdx.x;
    const int warp = tid >> 5;
    const int lane = tid & 31;
    const int g    = lane >> 2;
    const int tg   = lane & 3;
    const int par  = warp >> 2;          // k-step parity (0/1)
    const int blk  = warp & 3;           // which 32x32 block of G
    const int r0   = (blk >> 1) * 32;    // output row base
    const int d0   = (blk & 1) * 32;     // output col base

    const float* xb   = x + (size_t)b * NB_;
    const int   nbase = blockIdx.x * (G_CHUNKS * 64);

    const int lrow = tid >> 4;           // rows tid/16, +16, +32, +48
    const int lc4  = (tid & 15) << 2;

    float acc[2][4][4];
#pragma unroll
    for (int m = 0; m < 2; m++)
#pragma unroll
        for (int i = 0; i < 4; i++)
#pragma unroll
            for (int j = 0; j < 4; j++) acc[m][i][j] = 0.0f;

    // prologue: prefetch chunks 0 and 1
#pragma unroll
    for (int pf = 0; pf < 2; pf++) {
        const float* gsrc = xb + nbase + pf * 64;
        float* buf = Ks + pf * (64 * S1);
#pragma unroll
        for (int it = 0; it < 4; it++) {
            int row = lrow + it * 16;
            cp_async16(smem_u32(&buf[row * S1 + lc4]),
                       gsrc + (size_t)row * N_ + lc4);
        }
        cp_commit();
    }

    for (int ch = 0; ch < G_CHUNKS; ch++) {
        cp_wait<1>();          // chunk ch resident
        __syncthreads();

        const float* buf = Ks + (ch % 3) * (64 * S1);
#pragma unroll
        for (int ksl = 0; ksl < 4; ksl++) {
            const int kk = (ksl * 2 + par) * 8;
            uint32_t a[2][4];
#pragma unroll
            for (int m = 0; m < 2; m++) {
                const int rm = r0 + m * 16;
                a[m][0] = f2u(buf[(rm + g)     * S1 + kk + tg]);
                a[m][1] = f2u(buf[(rm + 8 + g) * S1 + kk + tg]);
                a[m][2] = f2u(buf[(rm + g)     * S1 + kk + tg + 4]);
                a[m][3] = f2u(buf[(rm + 8 + g) * S1 + kk + tg + 4]);
            }
#pragma unroll
            for (int nb = 0; nb < 4; nb++) {
                const int dr = d0 + nb * 8 + g;
                uint32_t b0 = f2u(buf[dr * S1 + kk + tg]);
                uint32_t b1 = f2u(buf[dr * S1 + kk + tg + 4]);
#pragma unroll
                for (int m = 0; m < 2; m++)
                    mma_tf32(acc[m][nb][0], acc[m][nb][1],
                             acc[m][nb][2], acc[m][nb][3],
                             a[m][0], a[m][1], a[m][2], a[m][3], b0, b1);
            }
        }

        // prefetch chunk ch+2 (off the critical compute-entry path)
        if (ch + 2 < G_CHUNKS) {
            const float* gsrc = xb + nbase + (ch + 2) * 64;
            float* pbuf = Ks + ((ch + 2) % 3) * (64 * S1);
#pragma unroll
            for (int it = 0; it < 4; it++) {
                int row = lrow + it * 16;
                cp_async16(smem_u32(&pbuf[row * S1 + lc4]),
                           gsrc + (size_t)row * N_ + lc4);
            }
        }
        cp_commit();           // always commit -> uniform wait counting
    }

    // merge partials (parity pairs + 72 CTAs hit the same entries)
    float* Gb = g_G + b * (C_ * C_);
#pragma unroll
    for (int m = 0; m < 2; m++) {
        const int rA = r0 + m * 16 + g;
        const int rB = rA + 8;
#pragma unroll
        for (int nb = 0; nb < 4; nb++) {
            const int d = d0 + nb * 8 + tg * 2;
            atomicAdd(&Gb[rA * C_ + d],     acc[m][nb][0]);
            atomicAdd(&Gb[rA * C_ + d + 1], acc[m][nb][1]);
            atomicAdd(&Gb[rB * C_ + d],     acc[m][nb][2]);
            atomicAdd(&Gb[rB * C_ + d + 1], acc[m][nb][3]);
        }
    }
}

// ---------------------------------------------------------------------------
// Kernel 2: out = x + gamma * (sigmoid(G@G) @ K)    [m3+sigmoid fused]
// grid (54, 8), block 256, *** 4 CTAs/SM via 2-STAGE pipeline ***.
// smem: 2 x Ks[64][72] = 36.9KB/CTA -> 147KB/SM, L1 keeps 81KB (avoids the
// measured 221KB bad zone). 32 warps/SM vs 24 -> +33% issue & latency hiding.
// Single-sync 2-stage loop:
//   wait<0>; __syncthreads; prefetch(t+1)->buf[(t+1)&1]; commit; compute(t)
// Correctness: the sync (a) is AFTER wait -> tile t visible to all threads;
// (b) every warp arrives having finished compute(t-1) (last op of iter t-1),
// the last reader of buffer (t+1)&1 -> prefetch into it is race-free.
// One-tile prefetch lead: load(t+1) (~1us) runs under compute(t) (~2.5us).
// Affinity fragments bf16x2-packed (16 regs) to fit the 64-reg cap at
// 4 CTAs/SM; bf16 error enters scaled by gamma=1e-4 -> ~1e-8 relative.
// GA (G/affinity [64][68]) overlays buffer 1; first overwritten by iter-0's
// prefetch of tile 1, which is ordered after iter-0's sync (all threads done
// extracting af). Last-arriver CTA re-zeroes g_G[b] (reads barrier-ordered
// before counter increment -> race-free).
// B-frag banks: 8tg+g+const bijective (S3=72 == 8 mod 32), conflict-free.
// ---------------------------------------------------------------------------
#define S3 72
#define SA 68
#define A_TILES 32
__global__ __launch_bounds__(256, 4)
void apply_kernel(const float* __restrict__ x, float* __restrict__ out,
                  const float* __restrict__ gammap)
{
    extern __shared__ float Ks[];        // 2 * 64 * 72 floats = 36864 B
    float* GA = Ks + 1 * (64 * S3);      // G / affinity region, [64][SA]
    __shared__ int sm_last;

    const int b    = blockIdx.y;
    const int tid  = threadIdx.x;
    const int warp = tid >> 5;
    const int lane = tid & 31;
    const int g    = lane >> 2;
    const int tg   = lane & 3;
    const int c0   = (warp >> 1) * 16;   // c-block (16 rows)
    const int nc0  = (warp & 1) * 32;    // n-half (32 cols)

    const float gamma = gammap[0];
    const float* xb   = x + (size_t)b * NB_;
    float*       ob   = out + (size_t)b * NB_;
    const int   nbase = blockIdx.x * (A_TILES * 64);

    const int lrow = tid >> 4;
    const int lc4  = (tid & 15) << 2;

    // prologue: prefetch tile 0 into buffer 0 (overlaps affinity phase)
    {
        const float* gsrc = xb + nbase;
#pragma unroll
        for (int it = 0; it < 4; it++) {
            int row = lrow + it * 16;
            cp_async16(smem_u32(&Ks[row * S3 + lc4]),
                       gsrc + (size_t)row * N_ + lc4);
        }
        cp_commit();
    }

    // ---- fused affinity = sigmoid(G @ G) in GA (= buffer 1 region) ----
    for (int i = tid; i < C_ * C_; i += 256)
        GA[(i >> 6) * SA + (i & 63)] = g_G[b * C_ * C_ + i];
    __syncthreads();   // all reads of g_G done for every thread of this CTA

    // arrival counter: g_G[b] may be zeroed once all 54 CTAs have read it
    if (tid == 0)
        sm_last = (atomicAdd(&g_cnt[b], 1) == (int)gridDim.x - 1) ? 1 : 0;

    {
        float mac[4][4];
#pragma unroll
        for (int i = 0; i < 4; i++)
#pragma unroll
            for (int j = 0; j < 4; j++) mac[i][j] = 0.0f;

#pragma unroll
        for (int kd = 0; kd < 8; kd++) {
            const int d0 = kd * 8;
            uint32_t a0 = f2u(GA[(c0 + g)     * SA + d0 + tg]);
            uint32_t a1 = f2u(GA[(c0 + 8 + g) * SA + d0 + tg]);
            uint32_t a2 = f2u(GA[(c0 + g)     * SA + d0 + tg + 4]);
            uint32_t a3 = f2u(GA[(c0 + 8 + g) * SA + d0 + tg + 4]);
#pragma unroll
            for (int nb = 0; nb < 4; nb++) {
                const int col = nc0 + nb * 8;
                uint32_t b0 = f2u(GA[(d0 + tg)     * SA + col + g]);
                uint32_t b1 = f2u(GA[(d0 + tg + 4) * SA + col + g]);
                mma_tf32(mac[nb][0], mac[nb][1], mac[nb][2], mac[nb][3],
                         a0, a1, a2, a3, b0, b1);
            }
        }
        __syncthreads();   // all reads of G done before overwrite w/ affinity

#pragma unroll
        for (int nb = 0; nb < 4; nb++) {
            const int col = nc0 + nb * 8 + 2 * tg;
            GA[(c0 + g)     * SA + col]     = sigmoidf_(mac[nb][0]);
            GA[(c0 + g)     * SA + col + 1] = sigmoidf_(mac[nb][1]);
            GA[(c0 + 8 + g) * SA + col]     = sigmoidf_(mac[nb][2]);
            GA[(c0 + 8 + g) * SA + col + 1] = sigmoidf_(mac[nb][3]);
        }
    }
    __syncthreads();

    // hoist affinity fragments, bf16x2-packed: afp[kd][0]=(a0,a2),
    // afp[kd][1]=(a1,a3). 16 regs (vs 32 fp32) -> fits 64-reg cap at occ 4.
    uint32_t afp[8][2];
#pragma unroll
    for (int kd = 0; kd < 8; kd++) {
        const int d0 = kd * 8;
        float a0 = GA[(c0 + g)     * SA + d0 + tg];
        float a1 = GA[(c0 + 8 + g) * SA + d0 + tg];
        float a2 = GA[(c0 + g)     * SA + d0 + tg + 4];
        float a3 = GA[(c0 + 8 + g) * SA + d0 + tg + 4];
        afp[kd][0] = pack_bf16x2(a0, a2);
        afp[kd][1] = pack_bf16x2(a1, a3);
    }

    // last arriver zeroes g_G[b] for the next launch and resets the counter
    if (sm_last) {
        for (int i = tid; i < C_ * C_; i += 256)
            g_G[b * C_ * C_ + i] = 0.0f;
        if (tid == 0) g_cnt[b] = 0;
    }

    // ---- main loop: 2-stage, ONE sync per tile ----
    for (int t = 0; t < A_TILES; t++) {
        cp_wait<0>();              // tile t load complete (this thread's view)
        __syncthreads();           // publish tile t; all warps done compute(t-1)

        // prefetch tile t+1 into the buffer compute(t-1) just finished with
        if (t + 1 < A_TILES) {
            const float* gsrc = xb + nbase + (t + 1) * 64;
            float* pbuf = Ks + ((t + 1) & 1) * (64 * S3);
#pragma unroll
            for (int it = 0; it < 4; it++) {
                int row = lrow + it * 16;
                cp_async16(smem_u32(&pbuf[row * S3 + lc4]),
                           gsrc + (size_t)row * N_ + lc4);
            }
        }
        cp_commit();               // always commit -> uniform wait counting

        const float* buf = Ks + (t & 1) * (64 * S3);

        float acc[4][4];
#pragma unroll
        for (int i = 0; i < 4; i++)
#pragma unroll
            for (int j = 0; j < 4; j++) acc[i][j] = 0.0f;

#pragma unroll
        for (int kd = 0; kd < 8; kd++) {
            const int d0 = kd * 8;
            uint32_t a0 = unpk_lo(afp[kd][0]);
            uint32_t a1 = unpk_lo(afp[kd][1]);
            uint32_t a2 = unpk_hi(afp[kd][0]);
            uint32_t a3 = unpk_hi(afp[kd][1]);
#pragma unroll
            for (int nb = 0; nb < 4; nb++) {
                const int col = nc0 + nb * 8;
                uint32_t b0 = f2u(buf[(d0 + tg)     * S3 + col + g]);
                uint32_t b1 = f2u(buf[(d0 + tg + 4) * S3 + col + g]);
                mma_tf32(acc[nb][0], acc[nb][1], acc[nb][2], acc[nb][3],
                         a0, a1, a2, a3, b0, b1);
            }
        }

        // epilogue: out = x + gamma * weights (x re-read from smem tile)
        const int n0 = nbase + t * 64;
#pragma unroll
        for (int nb = 0; nb < 4; nb++) {
            const int col = nc0 + nb * 8 + tg * 2;
            const int r0 = c0 + g;
            const int r1 = c0 + 8 + g;
            float2 x0 = *(const float2*)&buf[r0 * S3 + col];
            float2 x1 = *(const float2*)&buf[r1 * S3 + col];
            float2 o0 = make_float2(fmaf(gamma, acc[nb][0], x0.x),
                                    fmaf(gamma, acc[nb][1], x0.y));
            float2 o1 = make_float2(fmaf(gamma, acc[nb][2], x1.x),
                                    fmaf(gamma, acc[nb][3], x1.y));
            *(float2*)(ob + (size_t)r0 * N_ + n0 + col) = o0;
            *(float2*)(ob + (size_t)r1 * N_ + n0 + col) = o1;
        }
    }
}

// ---------------------------------------------------------------------------
// Launch
// ---------------------------------------------------------------------------
extern "C" void kernel_launch(void* const* d_in, const int* in_sizes, int n_in,
                              void* d_out, int out_size)
{
    const float* x     = (const float*)d_in[0];
    const float* gamma = (const float*)d_in[1];
    float*       out   = (float*)d_out;

    (void)in_sizes; (void)n_in; (void)out_size;

    const int smem1 = 3 * 64 * S1 * (int)sizeof(float);   // 52224
    const int smem3 = 2 * 64 * S3 * (int)sizeof(float);   // 36864

    cudaFuncSetAttribute(gram_kernel,
                         cudaFuncAttributeMaxDynamicSharedMemorySize, smem1);
    cudaFuncSetAttribute(apply_kernel,
                         cudaFuncAttributeMaxDynamicSharedMemorySize, smem3);

    dim3 grid1(72, B_);                   // 72 * 24 chunks * 64 = 110592
    gram_kernel<<<grid1, 256, smem1>>>(x);

    dim3 grid3(54, B_);                   // 54 * 32 tiles * 64 = 110592
    apply_kernel<<<grid3, 256, smem3>>>(x, out, gamma);
}